// round 2
// baseline (speedup 1.0000x reference)
#include <cuda_runtime.h>

#define H     51
#define G     204          // 4*H gates
#define BB    8            // batch elements per CTA
#define TPB   256
#define NCTA  128          // 128 * 8 = 1024 batch
#define T_IN  512
#define T_FUT 64
#define T_TOT (T_IN + T_FUT)
#define CHUNK 64           // input staging chunk (timesteps)

struct __align__(16) Smem {
    // weights transposed to [k][g] so consecutive gate-threads read consecutive addrs
    float W1[H + 1][G];     // row 0 = W_ih1 (input dim 1), rows 1..51 = W_hh1^T
    float W2[2 * H][G];     // rows 0..50 = W_ih2^T (input=h1), 51..101 = W_hh2^T
    float W3[2 * H][G];
    float b1[G], b2[G], b3[G];
    float wlin[52];
    float blin;
    float pad0[3];
    // state in [k][b] layout: rows of 8 floats (32B) -> float4 broadcast reads
    float h1[H][BB];
    float c1[H][BB];
    float h2[H][BB];
    float c2[H][BB];
    float h3[H][BB];
    float c3[H][BB];
    float gbuf[BB][G];      // gates staging: thread g writes gbuf[b][g] (conflict-free)
    float xin[BB][CHUNK];   // staged input chunk
    float xcur[BB];         // current-step scalar input per batch elem
};

__device__ __forceinline__ float sigf(float x) {
    // 1/(1+e^-x); inf-safe with fast division
    return __fdividef(1.0f, 1.0f + __expf(-x));
}
__device__ __forceinline__ float tanh_(float x) {
    // 1 - 2/(e^{2x}+1); saturates correctly at +-1
    return 1.0f - __fdividef(2.0f, __expf(2.0f * x) + 1.0f);
}

// accumulate acc[b] += W[k][g] * V[k][b] over k=0..H-1 (V rows broadcast via float4)
__device__ __forceinline__ void mac51(const float (*__restrict__ W)[G],
                                      const float (*__restrict__ V)[BB],
                                      int g, float acc[BB]) {
#pragma unroll 3
    for (int k = 0; k < H; k++) {
        float  w = W[k][g];
        float4 a = *(const float4 *)(&V[k][0]);
        float4 b = *(const float4 *)(&V[k][4]);
        acc[0] = fmaf(w, a.x, acc[0]);
        acc[1] = fmaf(w, a.y, acc[1]);
        acc[2] = fmaf(w, a.z, acc[2]);
        acc[3] = fmaf(w, a.w, acc[3]);
        acc[4] = fmaf(w, b.x, acc[4]);
        acc[5] = fmaf(w, b.y, acc[5]);
        acc[6] = fmaf(w, b.z, acc[6]);
        acc[7] = fmaf(w, b.w, acc[7]);
    }
}

__device__ __forceinline__ void store_gates(Smem *s, int g, const float acc[BB]) {
#pragma unroll
    for (int b = 0; b < BB; b++) s->gbuf[b][g] = acc[b];
}

__device__ __forceinline__ void cell_update(float (*__restrict__ Hh)[BB],
                                            float (*__restrict__ C)[BB],
                                            const float (*__restrict__ gb)[G]) {
    for (int idx = threadIdx.x; idx < H * BB; idx += TPB) {
        int   b  = idx / H;
        int   j  = idx - b * H;
        float gi = gb[b][j];
        float gf = gb[b][j + H];
        float gg = gb[b][j + 2 * H];
        float go = gb[b][j + 3 * H];
        float cp = C[j][b];
        float cn = sigf(gf) * cp + sigf(gi) * tanh_(gg);
        float hn = sigf(go) * tanh_(cn);
        C[j][b]  = cn;
        Hh[j][b] = hn;
    }
}

__global__ void __launch_bounds__(TPB, 1)
lstm_seq_kernel(const float *__restrict__ input,
                const float *__restrict__ W_ih1, const float *__restrict__ W_hh1,
                const float *__restrict__ b_ih1, const float *__restrict__ b_hh1,
                const float *__restrict__ W_ih2, const float *__restrict__ W_hh2,
                const float *__restrict__ b_ih2, const float *__restrict__ b_hh2,
                const float *__restrict__ W_ih3, const float *__restrict__ W_hh3,
                const float *__restrict__ b_ih3, const float *__restrict__ b_hh3,
                const float *__restrict__ W_lin, const float *__restrict__ b_lin,
                float *__restrict__ out) {
    extern __shared__ char raw[];
    Smem *s = (Smem *)raw;

    const int tid = threadIdx.x;
    const int b0  = blockIdx.x * BB;

    // ---- one-time weight staging (transpose to [k][g]) ----
    for (int idx = tid; idx < G; idx += TPB) {
        s->W1[0][idx] = W_ih1[idx];
        s->b1[idx]    = b_ih1[idx] + b_hh1[idx];
        s->b2[idx]    = b_ih2[idx] + b_hh2[idx];
        s->b3[idx]    = b_ih3[idx] + b_hh3[idx];
    }
    for (int idx = tid; idx < G * H; idx += TPB) {
        int g = idx / H;
        int k = idx - g * H;
        s->W1[1 + k][g] = W_hh1[idx];
        s->W2[k][g]     = W_ih2[idx];
        s->W2[H + k][g] = W_hh2[idx];
        s->W3[k][g]     = W_ih3[idx];
        s->W3[H + k][g] = W_hh3[idx];
    }
    if (tid < H) s->wlin[tid] = W_lin[tid];
    if (tid == 0) s->blin = b_lin[0];
    // zero all six state arrays (contiguous in the struct)
    for (int idx = tid; idx < 6 * H * BB; idx += TPB) (&s->h1[0][0])[idx] = 0.0f;
    __syncthreads();

    for (int t = 0; t < T_TOT; t++) {
        if (t < T_IN) {
            if ((t & (CHUNK - 1)) == 0) {
                // stage next CHUNK timesteps of input: 8 rows x 64 cols
                int          row = tid >> 5;
                int          col = (tid & 31) * 2;
                const float2 v =
                    *(const float2 *)&input[(size_t)(b0 + row) * T_IN + t + col];
                *(float2 *)&s->xin[row][col] = v;
                __syncthreads();
            }
            if (tid < BB) s->xcur[tid] = s->xin[tid][t & (CHUNK - 1)];
        }
        __syncthreads();

        // ---- layer 1 gates: x (k=0) + h1 (51) ----
        if (tid < G) {
            float acc[BB];
            float bias = s->b1[tid];
            float w0   = s->W1[0][tid];
            float4 xa  = *(const float4 *)&s->xcur[0];
            float4 xb  = *(const float4 *)&s->xcur[4];
            acc[0] = fmaf(w0, xa.x, bias);
            acc[1] = fmaf(w0, xa.y, bias);
            acc[2] = fmaf(w0, xa.z, bias);
            acc[3] = fmaf(w0, xa.w, bias);
            acc[4] = fmaf(w0, xb.x, bias);
            acc[5] = fmaf(w0, xb.y, bias);
            acc[6] = fmaf(w0, xb.z, bias);
            acc[7] = fmaf(w0, xb.w, bias);
            mac51(&s->W1[1], s->h1, tid, acc);
            store_gates(s, tid, acc);
        }
        __syncthreads();
        cell_update(s->h1, s->c1, s->gbuf);
        __syncthreads();

        // ---- layer 2 gates: h1 (51) + h2 (51) ----
        if (tid < G) {
            float acc[BB];
            float bias = s->b2[tid];
#pragma unroll
            for (int b = 0; b < BB; b++) acc[b] = bias;
            mac51(&s->W2[0], s->h1, tid, acc);
            mac51(&s->W2[H], s->h2, tid, acc);
            store_gates(s, tid, acc);
        }
        __syncthreads();
        cell_update(s->h2, s->c2, s->gbuf);
        __syncthreads();

        // ---- layer 3 gates: h2 (51) + h3 (51) ----
        if (tid < G) {
            float acc[BB];
            float bias = s->b3[tid];
#pragma unroll
            for (int b = 0; b < BB; b++) acc[b] = bias;
            mac51(&s->W3[0], s->h2, tid, acc);
            mac51(&s->W3[H], s->h3, tid, acc);
            store_gates(s, tid, acc);
        }
        __syncthreads();
        cell_update(s->h3, s->c3, s->gbuf);
        __syncthreads();

        // ---- linear head: out[b] = h3[:,b] . wlin + blin ----
        if (tid < 64) {
            int   b = tid >> 3, r = tid & 7;
            float sum = 0.0f;
            for (int j = r; j < H; j += 8) sum = fmaf(s->wlin[j], s->h3[j][b], sum);
            sum += __shfl_down_sync(0xffffffffu, sum, 4, 8);
            sum += __shfl_down_sync(0xffffffffu, sum, 2, 8);
            sum += __shfl_down_sync(0xffffffffu, sum, 1, 8);
            if (r == 0) {
                float v = sum + s->blin;
                out[(size_t)(b0 + b) * T_TOT + t] = v;
                if (t >= T_IN - 1) s->xcur[b] = v;  // autoregressive feed
            }
        }
        // loop-top __syncthreads orders xcur write vs next-step reads
    }
}

extern "C" void kernel_launch(void *const *d_in, const int *in_sizes, int n_in,
                              void *d_out, int out_size) {
    (void)in_sizes; (void)n_in; (void)out_size;
    cudaFuncSetAttribute(lstm_seq_kernel,
                         cudaFuncAttributeMaxDynamicSharedMemorySize,
                         (int)sizeof(Smem));
    lstm_seq_kernel<<<NCTA, TPB, sizeof(Smem)>>>(
        (const float *)d_in[0],
        (const float *)d_in[1], (const float *)d_in[2],
        (const float *)d_in[3], (const float *)d_in[4],
        (const float *)d_in[5], (const float *)d_in[6],
        (const float *)d_in[7], (const float *)d_in[8],
        (const float *)d_in[9], (const float *)d_in[10],
        (const float *)d_in[11], (const float *)d_in[12],
        (const float *)d_in[13], (const float *)d_in[14],
        (float *)d_out);
}